// round 5
// baseline (speedup 1.0000x reference)
#include <cuda_runtime.h>

namespace {

constexpr int Bn = 131072;   // batch rows
constexpr int TM = 48;       // rows per CTA
constexpr int NT = 256;      // threads per CTA
constexpr int NE = 4;        // experts
constexpr int CHUNK = 2048;  // floats per weight-staging chunk (8KB)

struct SmemT {
    float xs[TM][8];          // x tile (5 used, padded)
    float w1s[5 * 512];       // bW1 cached
    float a1[TM * 512];       // backbone h1 / expert gather buffer
    float a2[TM * 256];       // shared features
    float c1[TM * 128];
    float c2[TM * 128];
    float wst[2 * CHUNK];     // double-buffered weight staging (16KB)
    float cls[TM][4];
    int   elist[NE][TM];
    int   ecnt[NE];
};

struct Params {
    const float *x, *bW1, *bb1, *bg1, *bbt1, *bW2, *bb2, *bg2, *bbt2;
    const float *cW1, *cb1, *cg1, *cbt1, *cW2, *cb2, *cg2, *cbt2, *chW, *chb;
    const float *rW1, *rb1, *rg1, *rbt1, *rW2, *rb2, *rg2, *rbt2, *rhW, *rhb;
    float* out;
};

// out[row][N] = act[row][K] @ W[K][N] + bias, for row < nrows.
// Strided row map: row = rg + i*RG  (balances small nrows across SMSPs).
// Weight staging double-buffered: LDG next chunk -> compute -> STS -> bar.
// Caller need NOT sync before: the post-prologue bar orders act reads.
template<int K, int N, int RT, int CT>
__device__ __forceinline__ void gemm(const float* __restrict__ W,
                                     const float* __restrict__ bias,
                                     const float* act, float* out,
                                     float* wst, int nrows) {
    constexpr int KC = CHUNK / N;      // k-rows per chunk
    constexpr int NCH = K / KC;        // number of chunks
    constexpr int CG = N / CT;
    constexpr int RG = NT / CG;
    static_assert(RG * RT == TM, "row coverage");
    static_assert(CT == 4, "CT=4 float4 path");

    const int tid = threadIdx.x;
    const int cg = tid % CG;
    const int rg = tid / CG;
    const int j0 = cg * CT;

    float acc[RT][CT];
#pragma unroll
    for (int i = 0; i < RT; i++)
#pragma unroll
        for (int j = 0; j < CT; j++) acc[i][j] = 0.f;

    const float4* Wv = reinterpret_cast<const float4*>(W);

    // prologue: stage chunk 0 (each thread: 8 floats = 2 float4)
    {
        float4 p0 = Wv[tid * 2 + 0];
        float4 p1 = Wv[tid * 2 + 1];
        float4* w4 = reinterpret_cast<float4*>(wst);
        w4[tid * 2 + 0] = p0;
        w4[tid * 2 + 1] = p1;
    }
    __syncthreads();

    for (int c = 0; c < NCH; c++) {
        const float* cur = wst + (c & 1) * CHUNK;
        float4 q0, q1;
        const bool more = (c + 1 < NCH);
        if (more) {
            q0 = Wv[(c + 1) * (CHUNK / 4) + tid * 2 + 0];
            q1 = Wv[(c + 1) * (CHUNK / 4) + tid * 2 + 1];
        }

#pragma unroll
        for (int k4 = 0; k4 < KC; k4 += 4) {
            float4 wrow[4];
#pragma unroll
            for (int t = 0; t < 4; t++)
                wrow[t] = *reinterpret_cast<const float4*>(&cur[(k4 + t) * N + j0]);
#pragma unroll
            for (int i = 0; i < RT; i++) {
                const int row = rg + i * RG;
                if (row < nrows) {
                    float4 av = *reinterpret_cast<const float4*>(
                        &act[row * K + c * KC + k4]);
                    float avc[4] = {av.x, av.y, av.z, av.w};
#pragma unroll
                    for (int t = 0; t < 4; t++) {
                        acc[i][0] = fmaf(avc[t], wrow[t].x, acc[i][0]);
                        acc[i][1] = fmaf(avc[t], wrow[t].y, acc[i][1]);
                        acc[i][2] = fmaf(avc[t], wrow[t].z, acc[i][2]);
                        acc[i][3] = fmaf(avc[t], wrow[t].w, acc[i][3]);
                    }
                }
            }
        }

        if (more) {
            float4* n4 = reinterpret_cast<float4*>(wst + ((c + 1) & 1) * CHUNK);
            n4[tid * 2 + 0] = q0;
            n4[tid * 2 + 1] = q1;
        }
        __syncthreads();
    }

#pragma unroll
    for (int i = 0; i < RT; i++) {
        const int row = rg + i * RG;
        if (row < nrows) {
#pragma unroll
            for (int j = 0; j < CT; j++)
                out[row * N + j0 + j] = acc[i][j] + bias[j0 + j];
        }
    }
}

// In-place LayerNorm + ReLU over rows of length N (compact stride N).
template<int N>
__device__ __forceinline__ void ln_relu(float* buf, const float* __restrict__ g,
                                        const float* __restrict__ bt, int rows) {
    const int warp = threadIdx.x >> 5;
    const int lane = threadIdx.x & 31;
    for (int r = warp; r < rows; r += NT / 32) {
        float* row = buf + r * N;
        float s = 0.f;
#pragma unroll
        for (int j = lane; j < N; j += 32) s += row[j];
#pragma unroll
        for (int o = 16; o > 0; o >>= 1) s += __shfl_xor_sync(0xffffffffu, s, o);
        const float m = s * (1.0f / N);
        float v = 0.f;
#pragma unroll
        for (int j = lane; j < N; j += 32) { float d = row[j] - m; v = fmaf(d, d, v); }
#pragma unroll
        for (int o = 16; o > 0; o >>= 1) v += __shfl_xor_sync(0xffffffffu, v, o);
        const float rs = rsqrtf(v * (1.0f / N) + 1e-5f);
#pragma unroll
        for (int j = lane; j < N; j += 32) {
            float val = (row[j] - m) * rs * g[j] + bt[j];
            row[j] = val > 0.f ? val : 0.f;
        }
    }
}

__global__ void __launch_bounds__(NT, 1)
moe_kernel(Params p) {
    extern __shared__ char smem_raw[];
    SmemT& s = *reinterpret_cast<SmemT*>(smem_raw);
    const int tid = threadIdx.x;
    const int row0 = blockIdx.x * TM;
    const int nrows = min(TM, Bn - row0);

    for (int i = tid; i < nrows * 5; i += NT) s.xs[i / 5][i % 5] = p.x[(size_t)row0 * 5 + i];
    for (int i = tid; i < 5 * 512; i += NT) s.w1s[i] = p.bW1[i];
    __syncthreads();

    // ---- stage 1: [nrows,5] @ [5,512] ----
    for (int i = tid; i < nrows * 512; i += NT) {
        const int r = i >> 9, j = i & 511;
        float acc = p.bb1[j];
#pragma unroll
        for (int k = 0; k < 5; k++) acc = fmaf(s.xs[r][k], s.w1s[k * 512 + j], acc);
        s.a1[i] = acc;
    }
    __syncthreads();
    ln_relu<512>(s.a1, p.bg1, p.bbt1, nrows);

    // ---- stage 2: [nrows,512] @ [512,256] ----
    gemm<512, 256, 12, 4>(p.bW2, p.bb2, s.a1, s.a2, s.wst, nrows);
    __syncthreads();
    ln_relu<256>(s.a2, p.bg2, p.bbt2, nrows);

    // ---- class expert ----
    gemm<256, 128, 6, 4>(p.cW1, p.cb1, s.a2, s.c1, s.wst, nrows);
    __syncthreads();
    ln_relu<128>(s.c1, p.cg1, p.cbt1, nrows);
    gemm<128, 128, 6, 4>(p.cW2, p.cb2, s.c1, s.c2, s.wst, nrows);
    __syncthreads();
    ln_relu<128>(s.c2, p.cg2, p.cbt2, nrows);
    __syncthreads();

    // ---- class head (128->4), write class_out, route ----
    for (int i = tid; i < 512; i += NT) s.wst[i] = p.chW[i];
    __syncthreads();
    if (tid < nrows * 4) {
        const int r = tid >> 2, j = tid & 3;
        float acc = p.chb[j];
        const float* c2r = s.c2 + r * 128;
#pragma unroll 8
        for (int k = 0; k < 128; k++) acc = fmaf(c2r[k], s.wst[k * 4 + j], acc);
        s.cls[r][j] = acc;
        p.out[(size_t)(row0 + r) * 4 + j] = acc;
    }
    if (tid < NE) s.ecnt[tid] = 0;
    __syncthreads();
    if (tid == 0) {
        for (int r = 0; r < nrows; r++) {
            float best = s.cls[r][0]; int bi = 0;
#pragma unroll
            for (int j = 1; j < 4; j++)
                if (s.cls[r][j] > best) { best = s.cls[r][j]; bi = j; }
            s.elist[bi][s.ecnt[bi]++] = r;
        }
    }
    __syncthreads();

    // ---- reg experts: only the routed expert per row ----
    for (int e = 0; e < NE; e++) {
        const int ne = s.ecnt[e];
        if (ne == 0) continue;

        for (int i = tid; i < ne * 256; i += NT) {
            const int ri = i >> 8, j = i & 255;
            s.a1[ri * 256 + j] = s.a2[s.elist[e][ri] * 256 + j];
        }
        // gemm's internal post-prologue bar orders the gather before compute.

        gemm<256, 128, 6, 4>(p.rW1 + e * 256 * 128, p.rb1 + e * 128,
                             s.a1, s.c1, s.wst, ne);
        __syncthreads();
        ln_relu<128>(s.c1, p.rg1 + e * 128, p.rbt1 + e * 128, ne);
        gemm<128, 128, 6, 4>(p.rW2 + e * 128 * 128, p.rb2 + e * 128,
                             s.c1, s.c2, s.wst, ne);
        __syncthreads();
        ln_relu<128>(s.c2, p.rg2 + e * 128, p.rbt2 + e * 128, ne);
        __syncthreads();

        for (int i = tid; i < 384; i += NT) s.wst[i] = p.rhW[e * 384 + i];
        __syncthreads();
        if (tid < ne * 3) {
            const int i = tid / 3, j = tid - i * 3;
            float acc = p.rhb[e * 3 + j];
            const float* c2r = s.c2 + i * 128;
#pragma unroll 8
            for (int k = 0; k < 128; k++) acc = fmaf(c2r[k], s.wst[k * 3 + j], acc);
            s.cls[i][j] = acc;
        }
        __syncthreads();
        if (tid < ne) {
            const float v0 = s.cls[tid][0], v1 = s.cls[tid][1], v2 = s.cls[tid][2];
            const float m = fmaxf(v0, fmaxf(v1, v2));
            const float e0 = expf(v0 - m), e1 = expf(v1 - m), e2 = expf(v2 - m);
            const float inv = 1.f / (e0 + e1 + e2);
            const int gr = row0 + s.elist[e][tid];
            float* o = p.out + (size_t)Bn * 4 + (size_t)gr * 3;
            o[0] = e0 * inv; o[1] = e1 * inv; o[2] = e2 * inv;
        }
        __syncthreads();
    }
}

// ---------------------------------------------------------------------------
// Input-order detection (insertion order matched in round 4; kept as guard).
// ---------------------------------------------------------------------------
static const int SZ_A[29] = {655360,2560,512,512,512,131072,256,256,256,32768,
                             128,128,128,16384,128,128,128,512,4,131072,
                             512,512,512,65536,512,512,512,1536,12};
static const int PERM_A[29] = {0,1,2,3,4,5,6,7,8,9,10,11,12,13,14,15,16,17,18,
                               19,20,21,22,23,24,25,26,27,28};

static const int SZ_B[29] = {2560,131072,512,256,512,256,512,256,32768,16384,
                             128,128,128,128,128,128,512,4,131072,65536,
                             512,512,512,512,512,512,1536,12,655360};
static const int PERM_B[29] = {28,0,2,6,4,1,3,7,5,8,10,14,12,9,11,15,13,16,17,
                               18,20,24,22,19,21,25,23,26,27};

static const int SZ_C[29] = {512,256,512,256,512,256,2560,131072,128,128,128,
                             128,128,128,4,512,32768,16384,512,512,512,512,
                             512,512,12,1536,131072,65536,655360};
static const int PERM_C[29] = {28,6,0,4,2,7,1,5,3,16,8,12,10,17,9,13,11,15,14,
                               26,18,22,20,27,19,23,21,25,24};

}  // namespace

extern "C" void kernel_launch(void* const* d_in, const int* in_sizes, int n_in,
                              void* d_out, int out_size) {
    const int* perm = PERM_A;
    bool mA = true, mB = true, mC = true;
    for (int i = 0; i < 29 && i < n_in; i++) {
        if (in_sizes[i] != SZ_A[i]) mA = false;
        if (in_sizes[i] != SZ_B[i]) mB = false;
        if (in_sizes[i] != SZ_C[i]) mC = false;
    }
    if (mA) perm = PERM_A;
    else if (mB) perm = PERM_B;
    else if (mC) perm = PERM_C;

    const float* q[29];
    for (int i = 0; i < 29; i++) q[i] = (const float*)d_in[perm[i]];

    Params p;
    p.x    = q[0];  p.bW1  = q[1];  p.bb1  = q[2];  p.bg1  = q[3];  p.bbt1 = q[4];
    p.bW2  = q[5];  p.bb2  = q[6];  p.bg2  = q[7];  p.bbt2 = q[8];
    p.cW1  = q[9];  p.cb1  = q[10]; p.cg1  = q[11]; p.cbt1 = q[12];
    p.cW2  = q[13]; p.cb2  = q[14]; p.cg2  = q[15]; p.cbt2 = q[16];
    p.chW  = q[17]; p.chb  = q[18];
    p.rW1  = q[19]; p.rb1  = q[20]; p.rg1  = q[21]; p.rbt1 = q[22];
    p.rW2  = q[23]; p.rb2  = q[24]; p.rg2  = q[25]; p.rbt2 = q[26];
    p.rhW  = q[27]; p.rhb  = q[28];
    p.out  = (float*)d_out;

    cudaFuncSetAttribute(moe_kernel, cudaFuncAttributeMaxDynamicSharedMemorySize,
                         (int)sizeof(SmemT));
    const int grid = (Bn + TM - 1) / TM;
    moe_kernel<<<grid, NT, sizeof(SmemT)>>>(p);
}

// round 9
// speedup vs baseline: 1.1466x; 1.1466x over previous
#include <cuda_runtime.h>
#include <cstdint>

namespace {

constexpr int Bn = 131072;   // batch rows
constexpr int TM = 32;       // rows per CTA
constexpr int NT = 256;      // threads per CTA
constexpr int NE = 4;        // experts
constexpr int CHUNK = 4096;  // floats per weight-staging chunk (16KB)

struct SmemT {
    float xs[TM][8];          // x tile (5 used, padded)
    float w1s[5 * 512];       // bW1 cached
    float a1[TM * 512];       // backbone h1 / expert gather buffer
    float a2[TM * 256];       // shared features
    float c1[TM * 128];
    float c2[TM * 128];
    float wst[2 * CHUNK];     // double-buffered weight staging (32KB)
    float cls[TM][4];
    int   elist[NE][TM];
    int   ecnt[NE];
};

struct Params {
    const float *x, *bW1, *bb1, *bg1, *bbt1, *bW2, *bb2, *bg2, *bbt2;
    const float *cW1, *cb1, *cg1, *cbt1, *cW2, *cb2, *cg2, *cbt2, *chW, *chb;
    const float *rW1, *rb1, *rg1, *rbt1, *rW2, *rb2, *rg2, *rbt2, *rhW, *rhb;
    float* out;
};

__device__ __forceinline__ uint32_t smem_u32(const void* p) {
    return (uint32_t)__cvta_generic_to_shared(p);
}

__device__ __forceinline__ void cp_async16(uint32_t dst, const void* src) {
    asm volatile("cp.async.cg.shared.global [%0], [%1], 16;\n" :: "r"(dst), "l"(src));
}
__device__ __forceinline__ void cp_commit() {
    asm volatile("cp.async.commit_group;\n");
}
template<int G>
__device__ __forceinline__ void cp_wait() {
    asm volatile("cp.async.wait_group %0;\n" :: "n"(G));
}

// out[row][N] = act[row][K] @ W[K][N] + bias, for row < nrows.
// Strided row map row = rg + i*RG; rg is warp-uniform, so guards are uniform.
// Weights double-buffered through smem via cp.async; one barrier per chunk.
// NOTE: gemm's first internal __syncthreads orders caller's prior smem writes
// (activations) before any act reads here — callers need no pre-sync.
template<int K, int N, int RT, int CT>
__device__ __forceinline__ void gemm(const float* __restrict__ W,
                                     const float* __restrict__ bias,
                                     const float* act, float* out,
                                     float* wst, int nrows) {
    constexpr int KC = CHUNK / N;      // k-rows per chunk
    constexpr int NCH = (K * N) / CHUNK;
    constexpr int CG = N / CT;
    constexpr int RG = NT / CG;
    static_assert(RG * RT == TM, "row coverage");
    static_assert(KC <= K && (K % KC) == 0, "chunking");
    static_assert(CT == 4, "float4 path");

    const int tid = threadIdx.x;
    const int cg = tid % CG;
    const int rg = tid / CG;           // warp-uniform
    const int j0 = cg * CT;
    const uint32_t wst_b = smem_u32(wst);

    float acc[RT][CT];
#pragma unroll
    for (int i = 0; i < RT; i++)
#pragma unroll
        for (int j = 0; j < CT; j++) acc[i][j] = 0.f;

    // stage chunk 0
#pragma unroll
    for (int q = 0; q < 4; q++)
        cp_async16(wst_b + (uint32_t)(q * NT + tid) * 16,
                   W + (q * NT + tid) * 4);
    cp_commit();

    for (int c = 0; c < NCH; c++) {
        const float* cur = wst + (c & 1) * CHUNK;
        if (c + 1 < NCH) {
            const uint32_t db = wst_b + ((c + 1) & 1) * (CHUNK * 4);
            const float* Ws = W + (size_t)(c + 1) * CHUNK;
#pragma unroll
            for (int q = 0; q < 4; q++)
                cp_async16(db + (uint32_t)(q * NT + tid) * 16,
                           Ws + (q * NT + tid) * 4);
            cp_commit();
            cp_wait<1>();
        } else {
            cp_wait<0>();
        }
        __syncthreads();

#pragma unroll
        for (int k4 = 0; k4 < KC; k4 += 4) {
            float4 wrow[4];
#pragma unroll
            for (int t = 0; t < 4; t++)
                wrow[t] = *reinterpret_cast<const float4*>(&cur[(k4 + t) * N + j0]);
#pragma unroll
            for (int i = 0; i < RT; i++) {
                const int row = rg + i * RG;
                if (row < nrows) {   // warp-uniform
                    float4 av = *reinterpret_cast<const float4*>(
                        &act[row * K + c * KC + k4]);
                    float avc[4] = {av.x, av.y, av.z, av.w};
#pragma unroll
                    for (int t = 0; t < 4; t++) {
                        acc[i][0] = fmaf(avc[t], wrow[t].x, acc[i][0]);
                        acc[i][1] = fmaf(avc[t], wrow[t].y, acc[i][1]);
                        acc[i][2] = fmaf(avc[t], wrow[t].z, acc[i][2]);
                        acc[i][3] = fmaf(avc[t], wrow[t].w, acc[i][3]);
                    }
                }
            }
        }
        __syncthreads();  // all reads of cur done before next overwrite
    }

#pragma unroll
    for (int i = 0; i < RT; i++) {
        const int row = rg + i * RG;
        if (row < nrows) {
#pragma unroll
            for (int j = 0; j < CT; j++)
                out[row * N + j0 + j] = acc[i][j] + bias[j0 + j];
        }
    }
}

// In-place LayerNorm + ReLU over rows of length N (compact stride N).
template<int N>
__device__ __forceinline__ void ln_relu(float* buf, const float* __restrict__ g,
                                        const float* __restrict__ bt, int rows) {
    const int warp = threadIdx.x >> 5;
    const int lane = threadIdx.x & 31;
    for (int r = warp; r < rows; r += NT / 32) {
        float* row = buf + r * N;
        float s = 0.f;
#pragma unroll
        for (int j = lane; j < N; j += 32) s += row[j];
#pragma unroll
        for (int o = 16; o > 0; o >>= 1) s += __shfl_xor_sync(0xffffffffu, s, o);
        const float m = s * (1.0f / N);
        float v = 0.f;
#pragma unroll
        for (int j = lane; j < N; j += 32) { float d = row[j] - m; v = fmaf(d, d, v); }
#pragma unroll
        for (int o = 16; o > 0; o >>= 1) v += __shfl_xor_sync(0xffffffffu, v, o);
        const float rs = rsqrtf(v * (1.0f / N) + 1e-5f);
#pragma unroll
        for (int j = lane; j < N; j += 32) {
            float val = (row[j] - m) * rs * g[j] + bt[j];
            row[j] = val > 0.f ? val : 0.f;
        }
    }
}

__global__ void __launch_bounds__(NT, 1)
moe_kernel(Params p) {
    extern __shared__ char smem_raw[];
    SmemT& s = *reinterpret_cast<SmemT*>(smem_raw);
    const int tid = threadIdx.x;
    const int row0 = blockIdx.x * TM;

    for (int i = tid; i < TM * 5; i += NT) s.xs[i / 5][i % 5] = p.x[(size_t)row0 * 5 + i];
    for (int i = tid; i < 5 * 512; i += NT) s.w1s[i] = p.bW1[i];
    __syncthreads();

    // ---- stage 1: [TM,5] @ [5,512] ----
    for (int i = tid; i < TM * 512; i += NT) {
        const int r = i >> 9, j = i & 511;
        float acc = p.bb1[j];
#pragma unroll
        for (int k = 0; k < 5; k++) acc = fmaf(s.xs[r][k], s.w1s[k * 512 + j], acc);
        s.a1[i] = acc;
    }
    __syncthreads();
    ln_relu<512>(s.a1, p.bg1, p.bbt1, TM);

    // ---- stage 2: [TM,512] @ [512,256] ----
    gemm<512, 256, 8, 4>(p.bW2, p.bb2, s.a1, s.a2, s.wst, TM);
    __syncthreads();
    ln_relu<256>(s.a2, p.bg2, p.bbt2, TM);

    // ---- class expert ----
    gemm<256, 128, 4, 4>(p.cW1, p.cb1, s.a2, s.c1, s.wst, TM);
    __syncthreads();
    ln_relu<128>(s.c1, p.cg1, p.cbt1, TM);
    gemm<128, 128, 4, 4>(p.cW2, p.cb2, s.c1, s.c2, s.wst, TM);
    __syncthreads();
    ln_relu<128>(s.c2, p.cg2, p.cbt2, TM);
    __syncthreads();

    // ---- class head (128->4), write class_out, route (parallel) ----
    for (int i = tid; i < 512; i += NT) s.wst[i] = p.chW[i];
    if (tid < NE) s.ecnt[tid] = 0;
    __syncthreads();
    if (tid < TM * 4) {
        const int r = tid >> 2, j = tid & 3;
        float acc = p.chb[j];
        const float* c2r = s.c2 + r * 128;
#pragma unroll 8
        for (int k = 0; k < 128; k++) acc = fmaf(c2r[k], s.wst[k * 4 + j], acc);
        s.cls[r][j] = acc;
        p.out[(size_t)(row0 + r) * 4 + j] = acc;
    }
    __syncthreads();
    if (tid < TM) {
        const int r = tid;
        float best = s.cls[r][0]; int bi = 0;
#pragma unroll
        for (int j = 1; j < 4; j++)
            if (s.cls[r][j] > best) { best = s.cls[r][j]; bi = j; }
        const int slot = atomicAdd(&s.ecnt[bi], 1);
        s.elist[bi][slot] = r;
    }
    __syncthreads();

    // ---- reg experts: only the routed expert per row ----
    for (int e = 0; e < NE; e++) {
        const int ne = s.ecnt[e];
        if (ne == 0) continue;

        for (int i = tid; i < ne * 256; i += NT) {
            const int ri = i >> 8, j = i & 255;
            s.a1[ri * 256 + j] = s.a2[s.elist[e][ri] * 256 + j];
        }
        // gemm's internal barrier (after chunk-0 wait) orders the gather.

        gemm<256, 128, 4, 4>(p.rW1 + e * 256 * 128, p.rb1 + e * 128,
                             s.a1, s.c1, s.wst, ne);
        __syncthreads();
        ln_relu<128>(s.c1, p.rg1 + e * 128, p.rbt1 + e * 128, ne);
        gemm<128, 128, 4, 4>(p.rW2 + e * 128 * 128, p.rb2 + e * 128,
                             s.c1, s.c2, s.wst, ne);
        __syncthreads();
        ln_relu<128>(s.c2, p.rg2 + e * 128, p.rbt2 + e * 128, ne);
        __syncthreads();

        for (int i = tid; i < 384; i += NT) s.wst[i] = p.rhW[e * 384 + i];
        __syncthreads();
        if (tid < ne * 3) {
            const int i = tid / 3, j = tid - i * 3;
            float acc = p.rhb[e * 3 + j];
            const float* c2r = s.c2 + i * 128;
#pragma unroll 8
            for (int k = 0; k < 128; k++) acc = fmaf(c2r[k], s.wst[k * 3 + j], acc);
            s.cls[i][j] = acc;
        }
        __syncthreads();
        if (tid < ne) {
            const float v0 = s.cls[tid][0], v1 = s.cls[tid][1], v2 = s.cls[tid][2];
            const float m = fmaxf(v0, fmaxf(v1, v2));
            const float e0 = expf(v0 - m), e1 = expf(v1 - m), e2 = expf(v2 - m);
            const float inv = 1.f / (e0 + e1 + e2);
            const int gr = row0 + s.elist[e][tid];
            float* o = p.out + (size_t)Bn * 4 + (size_t)gr * 3;
            o[0] = e0 * inv; o[1] = e1 * inv; o[2] = e2 * inv;
        }
        __syncthreads();
    }
}

// ---------------------------------------------------------------------------
// Input-order detection (insertion order matched; kept as guard).
// ---------------------------------------------------------------------------
static const int SZ_A[29] = {655360,2560,512,512,512,131072,256,256,256,32768,
                             128,128,128,16384,128,128,128,512,4,131072,
                             512,512,512,65536,512,512,512,1536,12};
static const int PERM_A[29] = {0,1,2,3,4,5,6,7,8,9,10,11,12,13,14,15,16,17,18,
                               19,20,21,22,23,24,25,26,27,28};

static const int SZ_B[29] = {2560,131072,512,256,512,256,512,256,32768,16384,
                             128,128,128,128,128,128,512,4,131072,65536,
                             512,512,512,512,512,512,1536,12,655360};
static const int PERM_B[29] = {28,0,2,6,4,1,3,7,5,8,10,14,12,9,11,15,13,16,17,
                               18,20,24,22,19,21,25,23,26,27};

static const int SZ_C[29] = {512,256,512,256,512,256,2560,131072,128,128,128,
                             128,128,128,4,512,32768,16384,512,512,512,512,
                             512,512,12,1536,131072,65536,655360};
static const int PERM_C[29] = {28,6,0,4,2,7,1,5,3,16,8,12,10,17,9,13,11,15,14,
                               26,18,22,20,27,19,23,21,25,24};

}  // namespace

extern "C" void kernel_launch(void* const* d_in, const int* in_sizes, int n_in,
                              void* d_out, int out_size) {
    const int* perm = PERM_A;
    bool mA = true, mB = true, mC = true;
    for (int i = 0; i < 29 && i < n_in; i++) {
        if (in_sizes[i] != SZ_A[i]) mA = false;
        if (in_sizes[i] != SZ_B[i]) mB = false;
        if (in_sizes[i] != SZ_C[i]) mC = false;
    }
    if (mA) perm = PERM_A;
    else if (mB) perm = PERM_B;
    else if (mC) perm = PERM_C;

    const float* q[29];
    for (int i = 0; i < 29; i++) q[i] = (const float*)d_in[perm[i]];

    Params p;
    p.x    = q[0];  p.bW1  = q[1];  p.bb1  = q[2];  p.bg1  = q[3];  p.bbt1 = q[4];
    p.bW2  = q[5];  p.bb2  = q[6];  p.bg2  = q[7];  p.bbt2 = q[8];
    p.cW1  = q[9];  p.cb1  = q[10]; p.cg1  = q[11]; p.cbt1 = q[12];
    p.cW2  = q[13]; p.cb2  = q[14]; p.cg2  = q[15]; p.cbt2 = q[16];
    p.chW  = q[17]; p.chb  = q[18];
    p.rW1  = q[19]; p.rb1  = q[20]; p.rg1  = q[21]; p.rbt1 = q[22];
    p.rW2  = q[23]; p.rb2  = q[24]; p.rg2  = q[25]; p.rbt2 = q[26];
    p.rhW  = q[27]; p.rhb  = q[28];
    p.out  = (float*)d_out;

    cudaFuncSetAttribute(moe_kernel, cudaFuncAttributeMaxDynamicSharedMemorySize,
                         (int)sizeof(SmemT));
    moe_kernel<<<Bn / TM, NT, sizeof(SmemT)>>>(p);
}